// round 4
// baseline (speedup 1.0000x reference)
#include <cuda_runtime.h>
#include <math.h>

#define TRAJ_NUM 8
#define EVAL     30
#define SGM_T    2.0f
#define D0c      0.5f
#define Rc       0.3f
#define VOX      0.2f
#define INV_VOX  5.0f
#define BIGF     3.4e38f

#define MAXG 1024

// scratch (no allocations allowed)
__device__ int g_mn0[MAXG*3];
__device__ int g_mx0[MAXG*3];

// replay-safe grid barrier state
__device__ unsigned int g_count = 0;
__device__ volatile unsigned int g_gen = 0;

__device__ __forceinline__ float warpMinF(float v) {
    #pragma unroll
    for (int o = 16; o > 0; o >>= 1) v = fminf(v, __shfl_xor_sync(0xffffffff, v, o));
    return v;
}
__device__ __forceinline__ float warpMaxF(float v) {
    #pragma unroll
    for (int o = 16; o > 0; o >>= 1) v = fmaxf(v, __shfl_xor_sync(0xffffffff, v, o));
    return v;
}
__device__ __forceinline__ int warpMaxI(int v) {
    #pragma unroll
    for (int o = 16; o > 0; o >>= 1) v = max(v, __shfl_xor_sync(0xffffffff, v, o));
    return v;
}
__device__ __forceinline__ float warpSumF(float v) {
    #pragma unroll
    for (int o = 16; o > 0; o >>= 1) v += __shfl_xor_sync(0xffffffff, v, o);
    return v;
}

__global__ void __launch_bounds__(256, 2)
fused_kernel(const float* __restrict__ Df, const float* __restrict__ Dp,
             const float* __restrict__ L,  const float* __restrict__ sdf,
             const float* __restrict__ min_bounds,
             const float* __restrict__ sdf_shapes,
             const int* __restrict__ map_id,
             float* __restrict__ out, int G)
{
    const int g    = blockIdx.x;
    const int t    = threadIdx.x;
    const int w    = t >> 5;          // trajectory within group
    const int lane = t & 31;          // eval index
    const bool act = (lane < EVAL);
    const int b    = g * TRAJ_NUM + w;

    __shared__ float s_wmn[TRAJ_NUM][3], s_wmx[TRAJ_NUM][3];
    __shared__ int   s_mn[3], s_ls[3];

    const int mid = __ldg(&map_id[g]);

    // ---------------- Phase 1: position in registers ----------------------
    float p0 = 0.f, p1 = 0.f, p2 = 0.f;
    if (act) {
        const float start = SGM_T / (float)EVAL;
        const float step  = (SGM_T - start) / (float)(EVAL - 1);
        const float tn    = start + (float)lane * step;
        const float tn2 = tn*tn, tn3 = tn2*tn, tn4 = tn3*tn, tn5 = tn4*tn;

        float wk[6];
        #pragma unroll
        for (int k = 0; k < 6; k++) {
            wk[k] = __ldg(&L[k])
                  + tn  * __ldg(&L[ 6 + k])
                  + tn2 * __ldg(&L[12 + k])
                  + tn3 * __ldg(&L[18 + k])
                  + tn4 * __ldg(&L[24 + k])
                  + tn5 * __ldg(&L[30 + k]);
        }
        const float* df = Df + b*9;   // warp-uniform → broadcast loads
        const float* dp = Dp + b*9;
        p0 = wk[0]*__ldg(df+0) + wk[1]*__ldg(df+1) + wk[2]*__ldg(df+2)
           + wk[3]*__ldg(dp+0) + wk[4]*__ldg(dp+1) + wk[5]*__ldg(dp+2);
        p1 = wk[0]*__ldg(df+3) + wk[1]*__ldg(df+4) + wk[2]*__ldg(df+5)
           + wk[3]*__ldg(dp+3) + wk[4]*__ldg(dp+4) + wk[5]*__ldg(dp+5);
        p2 = wk[0]*__ldg(df+6) + wk[1]*__ldg(df+7) + wk[2]*__ldg(df+8)
           + wk[3]*__ldg(dp+6) + wk[4]*__ldg(dp+7) + wk[5]*__ldg(dp+8);
    }

    // per-warp AABB via shuffles
    {
        float v;
        v = act ? p0 :  BIGF; v = warpMinF(v); if (lane == 0) s_wmn[w][0] = v;
        v = act ? p1 :  BIGF; v = warpMinF(v); if (lane == 0) s_wmn[w][1] = v;
        v = act ? p2 :  BIGF; v = warpMinF(v); if (lane == 0) s_wmn[w][2] = v;
        v = act ? p0 : -BIGF; v = warpMaxF(v); if (lane == 0) s_wmx[w][0] = v;
        v = act ? p1 : -BIGF; v = warpMaxF(v); if (lane == 0) s_wmx[w][1] = v;
        v = act ? p2 : -BIGF; v = warpMaxF(v); if (lane == 0) s_wmx[w][2] = v;
    }
    __syncthreads();   // sync #1

    // ---------------- Warp 0: finish AABB, grid barrier, phase 2 ----------
    if (w == 0) {
        int m0own = 0, x0own = 0;
        if (lane < 3) {
            float vmn = BIGF, vmx = -BIGF;
            #pragma unroll
            for (int q = 0; q < TRAJ_NUM; q++) {
                vmn = fminf(vmn, s_wmn[q][lane]);
                vmx = fmaxf(vmx, s_wmx[q][lane]);
            }
            float mbl = __ldg(&min_bounds[mid*3 + lane]);
            m0own = (int)truncf((vmn - mbl) * INV_VOX);
            x0own = (int)truncf((vmx - mbl) * INV_VOX);
            g_mn0[g*3 + lane] = m0own;
            g_mx0[g*3 + lane] = x0own;
            __threadfence();
        }
        __syncwarp();
        if (lane == 0) {
            unsigned int gen = g_gen;
            if (atomicAdd(&g_count, 1) == gridDim.x - 1) {
                g_count = 0;
                __threadfence();
                g_gen = gen + 1;
            } else {
                while (g_gen == gen) { }
            }
            __threadfence();
        }
        __syncwarp();

        // phase 2a: max_spans over all groups (8 groups per lane)
        int ms0 = 0, ms1 = 0, ms2 = 0;
        for (int grp = lane; grp < G; grp += 32) {
            ms0 = max(ms0, g_mx0[grp*3+0] - g_mn0[grp*3+0]);
            ms1 = max(ms1, g_mx0[grp*3+1] - g_mn0[grp*3+1]);
            ms2 = max(ms2, g_mx0[grp*3+2] - g_mn0[grp*3+2]);
        }
        ms0 = warpMaxI(ms0); ms1 = warpMaxI(ms1); ms2 = warpMaxI(ms2);

        // phase 2b: shift over all groups
        int sh0 = 0, sh1 = 0, sh2 = 0;
        for (int grp = lane; grp < G; grp += 32) {
            int tmid = __ldg(&map_id[grp]);
            #pragma unroll
            for (int i = 0; i < 3; i++) {
                int tm0 = g_mn0[grp*3 + i];
                int tx0 = g_mx0[grp*3 + i];
                int shp = (int)__ldg(&sdf_shapes[tmid*3 + i]);
                int ms  = (i == 0) ? ms0 : ((i == 1) ? ms1 : ms2);
                int c   = (tm0 + tx0) >> 1;
                int mnl = c - (ms >> 1) - 5;
                int mxl = c + (ms >> 1) + 5;
                int nmn = max(mnl, 0);
                mxl += nmn - mnl; mnl = nmn;
                int nmx = min(mxl, shp);
                mnl -= mxl - nmx;
                int sc = max(-min(mnl, 0), 0);
                if (i == 0) sh0 = max(sh0, sc);
                else if (i == 1) sh1 = max(sh1, sc);
                else sh2 = max(sh2, sc);
            }
        }
        sh0 = warpMaxI(sh0); sh1 = warpMaxI(sh1); sh2 = warpMaxI(sh2);

        // own group's final box (lanes 0..2 hold m0own/x0own)
        if (lane < 3) {
            int ms  = (lane == 0) ? ms0 : ((lane == 1) ? ms1 : ms2);
            int sh  = (lane == 0) ? sh0 : ((lane == 1) ? sh1 : sh2);
            int shp = (int)__ldg(&sdf_shapes[mid*3 + lane]);
            int c   = (m0own + x0own) >> 1;
            int m   = c - (ms >> 1) - 5;
            int x   = c + (ms >> 1) + 5;
            int nm  = max(m, 0);
            x += nm - m; m = nm;
            int nx  = min(x, shp);
            m -= x - nx; x = nx;
            m += sh;
            s_mn[lane] = m;
            s_ls[lane] = x - m;
        }
    }
    __syncthreads();   // sync #2

    // ---------------- Phase 3: trilinear gather + cost ---------------------
    float cost = 0.f;
    if (act) {
        const int mn0 = s_mn[0], mn1 = s_mn[1], mn2 = s_mn[2];
        const int ls0 = s_ls[0], ls1 = s_ls[1], ls2 = s_ls[2];
        const float mb0 = __ldg(&min_bounds[mid*3+0]);
        const float mb1 = __ldg(&min_bounds[mid*3+1]);
        const float mb2 = __ldg(&min_bounds[mid*3+2]);
        const int Wm = (int)__ldg(&sdf_shapes[0]);
        const int Hm = (int)__ldg(&sdf_shapes[1]);
        const int Dm = (int)__ldg(&sdf_shapes[2]);
        const long base = (long)mid * Dm * Hm * Wm;

        float gx = (p0 - ((float)mn0 * VOX + mb0)) * INV_VOX;
        float gy = (p1 - ((float)mn1 * VOX + mb1)) * INV_VOX;
        float gz = (p2 - ((float)mn2 * VOX + mb2)) * INV_VOX;

        float gpx = 2.f * gx / (float)(ls0 - 1) - 1.f;
        float gpy = 2.f * gy / (float)(ls1 - 1) - 1.f;
        float gpz = 2.f * gz / (float)(ls2 - 1) - 1.f;
        bool valid = (gpx <  0.99f) && (gpx > -0.99f) &&
                     (gpy <  0.99f) && (gpy > -0.99f) &&
                     (gpz <  0.99f) && (gpz > -0.99f);

        if (valid) {
            float fx0 = floorf(gx), fy0 = floorf(gy), fz0 = floorf(gz);
            int l0x = (int)fx0, l0y = (int)fy0, l0z = (int)fz0;
            float f0 = gx - fx0, f1 = gy - fy0, f2 = gz - fz0;

            float wx[2] = {1.f - f0, f0};
            float wy[2] = {1.f - f1, f1};
            float wz[2] = {1.f - f2, f2};

            float acc = 0.f;
            #pragma unroll
            for (int dx = 0; dx < 2; dx++)
            #pragma unroll
            for (int dy = 0; dy < 2; dy++)
            #pragma unroll
            for (int dz = 0; dz < 2; dz++) {
                int ilx = l0x + dx, ily = l0y + dy, ilz = l0z + dz;
                bool inb = (ilx >= 0) && (ilx < ls0) &&
                           (ily >= 0) && (ily < ls1) &&
                           (ilz >= 0) && (ilz < ls2);
                int igx = min(max(ilx + mn0, 0), Wm - 1);
                int igy = min(max(ily + mn1, 0), Hm - 1);
                int igz = min(max(ilz + mn2, 0), Dm - 1);
                float val = __ldg(&sdf[base + ((long)igz * Hm + igy) * Wm + igx]);
                float wgt = wx[dx] * wy[dy] * wz[dz];
                acc += inb ? wgt * val : 0.f;
            }
            cost = __expf(-(acc - D0c) / Rc);
        }
    }

    // per-trajectory sum via warp shuffle (inactive lanes contribute 0)
    float s = warpSumF(cost);
    if (lane == 0)
        out[g*TRAJ_NUM + w] = s * (SGM_T / (float)EVAL);
}

// ---------------------------------------------------------------------------
extern "C" void kernel_launch(void* const* d_in, const int* in_sizes, int n_in,
                              void* d_out, int out_size)
{
    const float* Df         = (const float*)d_in[0];
    const float* Dp         = (const float*)d_in[1];
    const float* L          = (const float*)d_in[2];
    const float* sdf_maps   = (const float*)d_in[3];
    const float* min_bounds = (const float*)d_in[4];
    const float* sdf_shapes = (const float*)d_in[5];
    const int*   map_id     = (const int*)d_in[6];

    int G = in_sizes[6];

    fused_kernel<<<G, 256>>>(Df, Dp, L, sdf_maps, min_bounds, sdf_shapes,
                             map_id, (float*)d_out, G);
}

// round 5
// speedup vs baseline: 1.3175x; 1.3175x over previous
#include <cuda_runtime.h>
#include <math.h>

#define TRAJ_NUM 8
#define EVAL     30
#define SGM_T    2.0f
#define D0c      0.5f
#define Rc       0.3f
#define VOX      0.2f
#define INV_VOX  5.0f
#define BIGF     3.4e38f

#define MAXG 1024

// scratch (no allocations allowed)
__device__ int g_mn0[MAXG*3];
__device__ int g_mx0[MAXG*3];
__device__ int g_mn [MAXG*3];
__device__ int g_ls [MAXG*3];

__device__ __forceinline__ float warpMinF(float v) {
    #pragma unroll
    for (int o = 16; o > 0; o >>= 1) v = fminf(v, __shfl_xor_sync(0xffffffff, v, o));
    return v;
}
__device__ __forceinline__ float warpMaxF(float v) {
    #pragma unroll
    for (int o = 16; o > 0; o >>= 1) v = fmaxf(v, __shfl_xor_sync(0xffffffff, v, o));
    return v;
}
__device__ __forceinline__ int warpMaxI(int v) {
    #pragma unroll
    for (int o = 16; o > 0; o >>= 1) v = max(v, __shfl_xor_sync(0xffffffff, v, o));
    return v;
}
__device__ __forceinline__ float warpSumF(float v) {
    #pragma unroll
    for (int o = 16; o > 0; o >>= 1) v += __shfl_xor_sync(0xffffffff, v, o);
    return v;
}

// position of eval point `lane` of trajectory b, in registers
__device__ __forceinline__ void traj_pos(
    const float* __restrict__ Df, const float* __restrict__ Dp,
    const float* __restrict__ L, int b, int lane,
    float& p0, float& p1, float& p2)
{
    const float start = SGM_T / (float)EVAL;
    const float step  = (SGM_T - start) / (float)(EVAL - 1);
    const float tn    = start + (float)lane * step;
    const float tn2 = tn*tn, tn3 = tn2*tn, tn4 = tn3*tn, tn5 = tn4*tn;

    float wk[6];
    #pragma unroll
    for (int k = 0; k < 6; k++) {
        wk[k] = __ldg(&L[k])
              + tn  * __ldg(&L[ 6 + k])
              + tn2 * __ldg(&L[12 + k])
              + tn3 * __ldg(&L[18 + k])
              + tn4 * __ldg(&L[24 + k])
              + tn5 * __ldg(&L[30 + k]);
    }
    const float* df = Df + b*9;   // warp-uniform -> broadcast loads
    const float* dp = Dp + b*9;
    p0 = wk[0]*__ldg(df+0) + wk[1]*__ldg(df+1) + wk[2]*__ldg(df+2)
       + wk[3]*__ldg(dp+0) + wk[4]*__ldg(dp+1) + wk[5]*__ldg(dp+2);
    p1 = wk[0]*__ldg(df+3) + wk[1]*__ldg(df+4) + wk[2]*__ldg(df+5)
       + wk[3]*__ldg(dp+3) + wk[4]*__ldg(dp+4) + wk[5]*__ldg(dp+5);
    p2 = wk[0]*__ldg(df+6) + wk[1]*__ldg(df+7) + wk[2]*__ldg(df+8)
       + wk[3]*__ldg(dp+6) + wk[4]*__ldg(dp+7) + wk[5]*__ldg(dp+8);
}

// ---------------------------------------------------------------------------
// Kernel A: per-group AABB (warp per trajectory, shuffle reduce, 1 sync)
// ---------------------------------------------------------------------------
__global__ void __launch_bounds__(256)
kernA(const float* __restrict__ Df, const float* __restrict__ Dp,
      const float* __restrict__ L,  const float* __restrict__ min_bounds,
      const int* __restrict__ map_id)
{
    const int g    = blockIdx.x;
    const int t    = threadIdx.x;
    const int w    = t >> 5;
    const int lane = t & 31;
    const bool act = (lane < EVAL);
    const int b    = g * TRAJ_NUM + w;

    __shared__ float s_wmn[TRAJ_NUM][3], s_wmx[TRAJ_NUM][3];

    float p0 = 0.f, p1 = 0.f, p2 = 0.f;
    if (act) traj_pos(Df, Dp, L, b, lane, p0, p1, p2);

    float v;
    v = act ? p0 :  BIGF; v = warpMinF(v); if (lane == 0) s_wmn[w][0] = v;
    v = act ? p1 :  BIGF; v = warpMinF(v); if (lane == 0) s_wmn[w][1] = v;
    v = act ? p2 :  BIGF; v = warpMinF(v); if (lane == 0) s_wmn[w][2] = v;
    v = act ? p0 : -BIGF; v = warpMaxF(v); if (lane == 0) s_wmx[w][0] = v;
    v = act ? p1 : -BIGF; v = warpMaxF(v); if (lane == 0) s_wmx[w][1] = v;
    v = act ? p2 : -BIGF; v = warpMaxF(v); if (lane == 0) s_wmx[w][2] = v;
    __syncthreads();

    if (w == 0 && lane < 3) {
        const int mid = __ldg(&map_id[g]);
        float vmn = BIGF, vmx = -BIGF;
        #pragma unroll
        for (int q = 0; q < TRAJ_NUM; q++) {
            vmn = fminf(vmn, s_wmn[q][lane]);
            vmx = fmaxf(vmx, s_wmx[q][lane]);
        }
        float mbl = __ldg(&min_bounds[mid*3 + lane]);
        g_mn0[g*3 + lane] = (int)truncf((vmn - mbl) * INV_VOX);
        g_mx0[g*3 + lane] = (int)truncf((vmx - mbl) * INV_VOX);
    }
}

// ---------------------------------------------------------------------------
// Kernel B: cross-group box logic, once (1 block, thread t = group t)
// ---------------------------------------------------------------------------
__global__ void __launch_bounds__(256)
kernB(const float* __restrict__ sdf_shapes, const int* __restrict__ map_id,
      int G)
{
    const int t    = threadIdx.x;
    const int wid  = t >> 5;
    const int lane = t & 31;
    const bool gact = (t < G);

    __shared__ int wred[8][3];
    __shared__ int s_ms[3], s_sh[3];

    int tm0[3] = {0,0,0}, tx0[3] = {0,0,0}, tshp[3] = {1,1,1};
    int span[3] = {0,0,0};
    if (gact) {
        int tmid = __ldg(&map_id[t]);
        #pragma unroll
        for (int i = 0; i < 3; i++) {
            tm0[i]  = g_mn0[t*3 + i];
            tx0[i]  = g_mx0[t*3 + i];
            tshp[i] = (int)__ldg(&sdf_shapes[tmid*3 + i]);
            span[i] = tx0[i] - tm0[i];
        }
    }
    #pragma unroll
    for (int i = 0; i < 3; i++) {
        int v = warpMaxI(span[i]);      // inactive contribute 0, span >= 0
        if (lane == 0) wred[wid][i] = v;
    }
    __syncthreads();
    if (t < 3) {
        int v = 0;
        #pragma unroll
        for (int q = 0; q < 8; q++) v = max(v, wred[q][t]);
        s_ms[t] = v;
    }
    __syncthreads();

    int sc[3] = {0,0,0};
    int mfin[3], xfin[3];
    if (gact) {
        #pragma unroll
        for (int i = 0; i < 3; i++) {
            int c   = (tm0[i] + tx0[i]) >> 1;
            int ms  = s_ms[i];
            int mnl = c - (ms >> 1) - 5;
            int mxl = c + (ms >> 1) + 5;
            int nmn = max(mnl, 0);
            mxl += nmn - mnl; mnl = nmn;
            int nmx = min(mxl, tshp[i]);
            mnl -= mxl - nmx; mxl = nmx;
            mfin[i] = mnl; xfin[i] = mxl;
            sc[i] = max(-min(mnl, 0), 0);
        }
    }
    #pragma unroll
    for (int i = 0; i < 3; i++) {
        int v = warpMaxI(sc[i]);        // inactive contribute 0, sc >= 0
        if (lane == 0) wred[wid][i] = v;
    }
    __syncthreads();
    if (t < 3) {
        int v = 0;
        #pragma unroll
        for (int q = 0; q < 8; q++) v = max(v, wred[q][t]);
        s_sh[t] = v;
    }
    __syncthreads();

    if (gact) {
        #pragma unroll
        for (int i = 0; i < 3; i++) {
            int m = mfin[i] + s_sh[i];
            g_mn[t*3 + i] = m;
            g_ls[t*3 + i] = xfin[i] - m;
        }
    }
}

// ---------------------------------------------------------------------------
// Kernel C: trilinear gather + cost + per-trajectory sum. NO block syncs.
// ---------------------------------------------------------------------------
__global__ void __launch_bounds__(256)
kernC(const float* __restrict__ Df, const float* __restrict__ Dp,
      const float* __restrict__ L,  const float* __restrict__ sdf,
      const float* __restrict__ min_bounds,
      const float* __restrict__ sdf_shapes,
      const int* __restrict__ map_id,
      float* __restrict__ out)
{
    const int g    = blockIdx.x;
    const int t    = threadIdx.x;
    const int w    = t >> 5;
    const int lane = t & 31;
    const bool act = (lane < EVAL);
    const int b    = g * TRAJ_NUM + w;

    const int mid = __ldg(&map_id[g]);

    float cost = 0.f;
    if (act) {
        float p0, p1, p2;
        traj_pos(Df, Dp, L, b, lane, p0, p1, p2);

        const int mn0 = __ldg(&g_mn[g*3+0]);
        const int mn1 = __ldg(&g_mn[g*3+1]);
        const int mn2 = __ldg(&g_mn[g*3+2]);
        const int ls0 = __ldg(&g_ls[g*3+0]);
        const int ls1 = __ldg(&g_ls[g*3+1]);
        const int ls2 = __ldg(&g_ls[g*3+2]);
        const float mb0 = __ldg(&min_bounds[mid*3+0]);
        const float mb1 = __ldg(&min_bounds[mid*3+1]);
        const float mb2 = __ldg(&min_bounds[mid*3+2]);
        const int Wm = (int)__ldg(&sdf_shapes[0]);
        const int Hm = (int)__ldg(&sdf_shapes[1]);
        const int Dm = (int)__ldg(&sdf_shapes[2]);
        const long base = (long)mid * Dm * Hm * Wm;

        float gx = (p0 - ((float)mn0 * VOX + mb0)) * INV_VOX;
        float gy = (p1 - ((float)mn1 * VOX + mb1)) * INV_VOX;
        float gz = (p2 - ((float)mn2 * VOX + mb2)) * INV_VOX;

        float gpx = 2.f * gx / (float)(ls0 - 1) - 1.f;
        float gpy = 2.f * gy / (float)(ls1 - 1) - 1.f;
        float gpz = 2.f * gz / (float)(ls2 - 1) - 1.f;
        bool valid = (gpx <  0.99f) && (gpx > -0.99f) &&
                     (gpy <  0.99f) && (gpy > -0.99f) &&
                     (gpz <  0.99f) && (gpz > -0.99f);

        if (valid) {
            float fx0 = floorf(gx), fy0 = floorf(gy), fz0 = floorf(gz);
            int l0x = (int)fx0, l0y = (int)fy0, l0z = (int)fz0;
            float f0 = gx - fx0, f1 = gy - fy0, f2 = gz - fz0;

            float wx[2] = {1.f - f0, f0};
            float wy[2] = {1.f - f1, f1};
            float wz[2] = {1.f - f2, f2};

            float acc = 0.f;
            #pragma unroll
            for (int dx = 0; dx < 2; dx++)
            #pragma unroll
            for (int dy = 0; dy < 2; dy++)
            #pragma unroll
            for (int dz = 0; dz < 2; dz++) {
                int ilx = l0x + dx, ily = l0y + dy, ilz = l0z + dz;
                bool inb = (ilx >= 0) && (ilx < ls0) &&
                           (ily >= 0) && (ily < ls1) &&
                           (ilz >= 0) && (ilz < ls2);
                int igx = min(max(ilx + mn0, 0), Wm - 1);
                int igy = min(max(ily + mn1, 0), Hm - 1);
                int igz = min(max(ilz + mn2, 0), Dm - 1);
                float val = __ldg(&sdf[base + ((long)igz * Hm + igy) * Wm + igx]);
                float wgt = wx[dx] * wy[dy] * wz[dz];
                acc += inb ? wgt * val : 0.f;
            }
            cost = __expf(-(acc - D0c) / Rc);
        }
    }

    float s = warpSumF(cost);
    if (lane == 0)
        out[g*TRAJ_NUM + w] = s * (SGM_T / (float)EVAL);
}

// ---------------------------------------------------------------------------
extern "C" void kernel_launch(void* const* d_in, const int* in_sizes, int n_in,
                              void* d_out, int out_size)
{
    const float* Df         = (const float*)d_in[0];
    const float* Dp         = (const float*)d_in[1];
    const float* L          = (const float*)d_in[2];
    const float* sdf_maps   = (const float*)d_in[3];
    const float* min_bounds = (const float*)d_in[4];
    const float* sdf_shapes = (const float*)d_in[5];
    const int*   map_id     = (const int*)d_in[6];

    int G = in_sizes[6];

    kernA<<<G, 256>>>(Df, Dp, L, min_bounds, map_id);
    kernB<<<1, 256>>>(sdf_shapes, map_id, G);
    kernC<<<G, 256>>>(Df, Dp, L, sdf_maps, min_bounds, sdf_shapes, map_id,
                      (float*)d_out);
}

// round 6
// speedup vs baseline: 1.3208x; 1.0025x over previous
#include <cuda_runtime.h>
#include <math.h>

#define TRAJ_NUM 8
#define EVAL     30
#define SGM_T    2.0f
#define D0c      0.5f
#define Rc       0.3f
#define VOX      0.2f
#define INV_VOX  5.0f
#define BIGF     3.4e38f

#define MAXG 1024

// scratch (no allocations allowed)
__device__ int g_mn0[MAXG*3];
__device__ int g_mx0[MAXG*3];

// replay-safe grid barrier state
__device__ unsigned int g_count = 0;
__device__ volatile unsigned int g_gen = 0;

__device__ __forceinline__ float warpMinF(float v) {
    #pragma unroll
    for (int o = 16; o > 0; o >>= 1) v = fminf(v, __shfl_xor_sync(0xffffffff, v, o));
    return v;
}
__device__ __forceinline__ float warpMaxF(float v) {
    #pragma unroll
    for (int o = 16; o > 0; o >>= 1) v = fmaxf(v, __shfl_xor_sync(0xffffffff, v, o));
    return v;
}
__device__ __forceinline__ int warpMaxI(int v) {
    #pragma unroll
    for (int o = 16; o > 0; o >>= 1) v = max(v, __shfl_xor_sync(0xffffffff, v, o));
    return v;
}
__device__ __forceinline__ float warpSumF(float v) {
    #pragma unroll
    for (int o = 16; o > 0; o >>= 1) v += __shfl_xor_sync(0xffffffff, v, o);
    return v;
}

__global__ void __launch_bounds__(256, 2)
fused_kernel(const float* __restrict__ Df, const float* __restrict__ Dp,
             const float* __restrict__ L,  const float* __restrict__ sdf,
             const float* __restrict__ min_bounds,
             const float* __restrict__ sdf_shapes,
             const int* __restrict__ map_id,
             float* __restrict__ out, int G)
{
    const int g    = blockIdx.x;
    const int t    = threadIdx.x;
    const int w    = t >> 5;          // trajectory within group
    const int lane = t & 31;          // eval index
    const bool act = (lane < EVAL);
    const int b    = g * TRAJ_NUM + w;

    __shared__ float s_wmn[TRAJ_NUM][3], s_wmx[TRAJ_NUM][3];
    __shared__ int   s_wred[8][3];
    __shared__ int   s_ms[3], s_sh[3];

    const int mid = __ldg(&map_id[g]);
    const float mb0 = __ldg(&min_bounds[mid*3+0]);
    const float mb1 = __ldg(&min_bounds[mid*3+1]);
    const float mb2 = __ldg(&min_bounds[mid*3+2]);
    const int Wm = (int)__ldg(&sdf_shapes[0]);
    const int Hm = (int)__ldg(&sdf_shapes[1]);
    const int Dm = (int)__ldg(&sdf_shapes[2]);
    const long base = (long)mid * Dm * Hm * Wm;

    // ---------------- Phase 1: positions + absolute grid -------------------
    float p0 = 0.f, p1 = 0.f, p2 = 0.f;
    if (act) {
        const float start = SGM_T / (float)EVAL;
        const float step  = (SGM_T - start) / (float)(EVAL - 1);
        const float tn    = start + (float)lane * step;
        const float tn2 = tn*tn, tn3 = tn2*tn, tn4 = tn3*tn, tn5 = tn4*tn;

        float wk[6];
        #pragma unroll
        for (int k = 0; k < 6; k++) {
            wk[k] = __ldg(&L[k])
                  + tn  * __ldg(&L[ 6 + k])
                  + tn2 * __ldg(&L[12 + k])
                  + tn3 * __ldg(&L[18 + k])
                  + tn4 * __ldg(&L[24 + k])
                  + tn5 * __ldg(&L[30 + k]);
        }
        const float* df = Df + b*9;   // warp-uniform -> broadcast loads
        const float* dp = Dp + b*9;
        p0 = wk[0]*__ldg(df+0) + wk[1]*__ldg(df+1) + wk[2]*__ldg(df+2)
           + wk[3]*__ldg(dp+0) + wk[4]*__ldg(dp+1) + wk[5]*__ldg(dp+2);
        p1 = wk[0]*__ldg(df+3) + wk[1]*__ldg(df+4) + wk[2]*__ldg(df+5)
           + wk[3]*__ldg(dp+3) + wk[4]*__ldg(dp+4) + wk[5]*__ldg(dp+5);
        p2 = wk[0]*__ldg(df+6) + wk[1]*__ldg(df+7) + wk[2]*__ldg(df+8)
           + wk[3]*__ldg(dp+6) + wk[4]*__ldg(dp+7) + wk[5]*__ldg(dp+8);
    }

    // absolute grid coords (box-independent)
    float ga0 = (p0 - mb0) * INV_VOX;
    float ga1 = (p1 - mb1) * INV_VOX;
    float ga2 = (p2 - mb2) * INV_VOX;
    float fl0 = floorf(ga0), fl1 = floorf(ga1), fl2 = floorf(ga2);
    int   li0 = (int)fl0,    li1 = (int)fl1,    li2 = (int)fl2;
    float f0  = ga0 - fl0,   f1  = ga1 - fl1,   f2  = ga2 - fl2;

    // -------- PREFETCH: issue all 8 gathers NOW (overlap with barrier) -----
    float v[8];
    if (act) {
        #pragma unroll
        for (int c = 0; c < 8; c++) {
            int dx = c & 1, dy = (c >> 1) & 1, dz = (c >> 2) & 1;
            int igx = min(max(li0 + dx, 0), Wm - 1);
            int igy = min(max(li1 + dy, 0), Hm - 1);
            int igz = min(max(li2 + dz, 0), Dm - 1);
            v[c] = __ldg(&sdf[base + ((long)igz * Hm + igy) * Wm + igx]);
        }
    } else {
        #pragma unroll
        for (int c = 0; c < 8; c++) v[c] = 0.f;
    }

    // ---------------- per-warp AABB of absolute grid coords ----------------
    {
        float x;
        x = act ? ga0 :  BIGF; x = warpMinF(x); if (lane == 0) s_wmn[w][0] = x;
        x = act ? ga1 :  BIGF; x = warpMinF(x); if (lane == 0) s_wmn[w][1] = x;
        x = act ? ga2 :  BIGF; x = warpMinF(x); if (lane == 0) s_wmn[w][2] = x;
        x = act ? ga0 : -BIGF; x = warpMaxF(x); if (lane == 0) s_wmx[w][0] = x;
        x = act ? ga1 : -BIGF; x = warpMaxF(x); if (lane == 0) s_wmx[w][1] = x;
        x = act ? ga2 : -BIGF; x = warpMaxF(x); if (lane == 0) s_wmx[w][2] = x;
    }
    __syncthreads();   // sync #1

    if (w == 0 && lane < 3) {
        float vmn = BIGF, vmx = -BIGF;
        #pragma unroll
        for (int q = 0; q < TRAJ_NUM; q++) {
            vmn = fminf(vmn, s_wmn[q][lane]);
            vmx = fmaxf(vmx, s_wmx[q][lane]);
        }
        g_mn0[g*3 + lane] = (int)truncf(vmn);
        g_mx0[g*3 + lane] = (int)truncf(vmx);
    }

    // ---------------- grid barrier (replay-safe) ---------------------------
    if (t == 0) {
        __threadfence();
        unsigned int gen = g_gen;
        if (atomicAdd(&g_count, 1) == gridDim.x - 1) {
            g_count = 0;
            __threadfence();
            g_gen = gen + 1;
        } else {
            while (g_gen == gen) { }
        }
        __threadfence();
    }
    __syncthreads();   // sync #2

    // ---------------- Phase 2: redundant cross-group box logic -------------
    // thread t handles group t (G = 256 here)
    int span[3] = {0,0,0};
    int tm0[3]  = {0,0,0}, tx0[3] = {0,0,0}, tshp[3] = {1,1,1};
    const bool gact = (t < G);
    if (gact) {
        int tmid = __ldg(&map_id[t]);
        #pragma unroll
        for (int i = 0; i < 3; i++) {
            tm0[i]  = g_mn0[t*3 + i];
            tx0[i]  = g_mx0[t*3 + i];
            tshp[i] = (int)__ldg(&sdf_shapes[tmid*3 + i]);
            span[i] = tx0[i] - tm0[i];
        }
    }
    #pragma unroll
    for (int i = 0; i < 3; i++) {
        int x = warpMaxI(span[i]);      // inactive contribute 0 (span >= 0)
        if (lane == 0) s_wred[w][i] = x;
    }
    __syncthreads();   // sync #3
    if (t < 3) {
        int x = 0;
        #pragma unroll
        for (int q = 0; q < 8; q++) x = max(x, s_wred[q][t]);
        s_ms[t] = x;
    }
    __syncthreads();   // sync #4

    int sc[3] = {0,0,0};
    if (gact) {
        #pragma unroll
        for (int i = 0; i < 3; i++) {
            int c   = (tm0[i] + tx0[i]) >> 1;
            int ms  = s_ms[i];
            int mnl = c - (ms >> 1) - 5;
            int mxl = c + (ms >> 1) + 5;
            int nmn = max(mnl, 0);
            mxl += nmn - mnl; mnl = nmn;
            int nmx = min(mxl, tshp[i]);
            mnl -= mxl - nmx;
            sc[i] = max(-min(mnl, 0), 0);
        }
    }
    #pragma unroll
    for (int i = 0; i < 3; i++) {
        int x = warpMaxI(sc[i]);        // inactive contribute 0 (sc >= 0)
        if (lane == 0) s_wred[w][i] = x;
    }
    __syncthreads();   // sync #5
    if (t < 3) {
        int x = 0;
        #pragma unroll
        for (int q = 0; q < 8; q++) x = max(x, s_wred[q][t]);
        s_sh[t] = x;
    }
    __syncthreads();   // sync #6

    // own group's final box (all threads compute identically; 6 L2-hit ints)
    int mn[3], ls[3];
    #pragma unroll
    for (int i = 0; i < 3; i++) {
        int m0  = g_mn0[g*3 + i];
        int x0  = g_mx0[g*3 + i];
        int shp = (i == 0) ? Wm : ((i == 1) ? Hm : Dm);
        int c   = (m0 + x0) >> 1;
        int ms  = s_ms[i];
        int m   = c - (ms >> 1) - 5;
        int x   = c + (ms >> 1) + 5;
        int nm  = max(m, 0);
        x += nm - m; m = nm;
        int nx  = min(x, shp);
        m -= x - nx; x = nx;
        m += s_sh[i];
        mn[i] = m;
        ls[i] = x - m;
    }

    // ---------------- Phase 3: combine prefetched corners ------------------
    float cost = 0.f;
    if (act) {
        // local grid exactly as reference for the validity test
        float gl0 = (p0 - ((float)mn[0] * VOX + mb0)) * INV_VOX;
        float gl1 = (p1 - ((float)mn[1] * VOX + mb1)) * INV_VOX;
        float gl2 = (p2 - ((float)mn[2] * VOX + mb2)) * INV_VOX;
        float gpx = 2.f * gl0 / (float)(ls[0] - 1) - 1.f;
        float gpy = 2.f * gl1 / (float)(ls[1] - 1) - 1.f;
        float gpz = 2.f * gl2 / (float)(ls[2] - 1) - 1.f;
        bool valid = (gpx <  0.99f) && (gpx > -0.99f) &&
                     (gpy <  0.99f) && (gpy > -0.99f) &&
                     (gpz <  0.99f) && (gpz > -0.99f);

        if (valid) {
            float wx[2] = {1.f - f0, f0};
            float wy[2] = {1.f - f1, f1};
            float wz[2] = {1.f - f2, f2};
            // local indices of prefetched cell
            int bx = li0 - mn[0], by = li1 - mn[1], bz = li2 - mn[2];

            float acc = 0.f;
            #pragma unroll
            for (int c = 0; c < 8; c++) {
                int dx = c & 1, dy = (c >> 1) & 1, dz = (c >> 2) & 1;
                int ilx = bx + dx, ily = by + dy, ilz = bz + dz;
                bool inb = (ilx >= 0) && (ilx < ls[0]) &&
                           (ily >= 0) && (ily < ls[1]) &&
                           (ilz >= 0) && (ilz < ls[2]);
                float wgt = wx[dx] * wy[dy] * wz[dz];
                acc += inb ? wgt * v[c] : 0.f;
            }
            cost = __expf(-(acc - D0c) / Rc);
        }
    }

    float s = warpSumF(cost);
    if (lane == 0)
        out[g*TRAJ_NUM + w] = s * (SGM_T / (float)EVAL);
}

// ---------------------------------------------------------------------------
extern "C" void kernel_launch(void* const* d_in, const int* in_sizes, int n_in,
                              void* d_out, int out_size)
{
    const float* Df         = (const float*)d_in[0];
    const float* Dp         = (const float*)d_in[1];
    const float* L          = (const float*)d_in[2];
    const float* sdf_maps   = (const float*)d_in[3];
    const float* min_bounds = (const float*)d_in[4];
    const float* sdf_shapes = (const float*)d_in[5];
    const int*   map_id     = (const int*)d_in[6];

    int G = in_sizes[6];

    fused_kernel<<<G, 256>>>(Df, Dp, L, sdf_maps, min_bounds, sdf_shapes,
                             map_id, (float*)d_out, G);
}